// round 2
// baseline (speedup 1.0000x reference)
#include <cuda_runtime.h>
#include <cstdint>

// Problem shape (fixed by reference): B=2, S=2048 -> ROWS=4096, n=m=4096
#define ROWS_T 4096
#define NDIM   4096
#define MDIM   4096
#define NCODE  (MDIM * (NDIM / 8))   // 2,097,152 codewords

// Scratch (allocation-free rule: __device__ globals)
__device__ float g_Xh[(size_t)ROWS_T * NDIM];   // Hadamard-rotated input (tf32-rounded)
__device__ float g_W [(size_t)MDIM   * NDIM];   // dequantized weights (tf32-rounded)

__device__ __forceinline__ float to_tf32(float x) {
    uint32_t u;
    asm("cvt.rna.tf32.f32 %0, %1;" : "=r"(u) : "f"(x));
    return __uint_as_float(u);
}

// ---------------------------------------------------------------------------
// Kernel 1: W = grid[Qidxs].reshape(m, n), rounded to tf32
// ---------------------------------------------------------------------------
__global__ void dequant_kernel(const float* __restrict__ grid,
                               const int*   __restrict__ qidxs,
                               float*       __restrict__ W) {
    int i = blockIdx.x * blockDim.x + threadIdx.x;
    if (i >= NCODE) return;
    int idx = qidxs[i];
    const float4* g4 = reinterpret_cast<const float4*>(grid) + (size_t)idx * 2;
    float4 a = g4[0], b = g4[1];
    float4 oa = make_float4(to_tf32(a.x), to_tf32(a.y), to_tf32(a.z), to_tf32(a.w));
    float4 ob = make_float4(to_tf32(b.x), to_tf32(b.y), to_tf32(b.z), to_tf32(b.w));
    float4* o4 = reinterpret_cast<float4*>(W) + (size_t)i * 2;
    o4[0] = oa; o4[1] = ob;
}

// ---------------------------------------------------------------------------
// Kernel 2: Xh[row] = tf32( FWHT(input[row] * SU) * (1/64) )
// One block per row, 1024 threads, full row in shared memory.
// ---------------------------------------------------------------------------
__global__ void fwht_su_kernel(const float* __restrict__ in,
                               const float* __restrict__ su,
                               float*       __restrict__ out) {
    __shared__ float s[NDIM];
    const int t = threadIdx.x;                 // 0..1023
    const size_t row = blockIdx.x;
    const float4* in4 = reinterpret_cast<const float4*>(in + row * NDIM);
    const float4* su4 = reinterpret_cast<const float4*>(su);
    float4 v = in4[t];
    float4 sc = su4[t];
    s[4*t+0] = v.x * sc.x;
    s[4*t+1] = v.y * sc.y;
    s[4*t+2] = v.z * sc.z;
    s[4*t+3] = v.w * sc.w;
    __syncthreads();
    #pragma unroll
    for (int h = 1; h < NDIM; h <<= 1) {
        #pragma unroll
        for (int p = t; p < NDIM / 2; p += 1024) {
            int i = ((p & ~(h - 1)) << 1) | (p & (h - 1));
            float a = s[i], b = s[i + h];
            s[i]     = a + b;
            s[i + h] = a - b;
        }
        __syncthreads();
    }
    float4 o;
    o.x = to_tf32(s[4*t+0] * 0.015625f);
    o.y = to_tf32(s[4*t+1] * 0.015625f);
    o.z = to_tf32(s[4*t+2] * 0.015625f);
    o.w = to_tf32(s[4*t+3] * 0.015625f);
    reinterpret_cast<float4*>(out + row * NDIM)[t] = o;
}

// ---------------------------------------------------------------------------
// Kernel 4: in-place row-FWHT on GEMM output, fused with SV * (1/64)
// ---------------------------------------------------------------------------
__global__ void fwht_sv_kernel(float* __restrict__ data,
                               const float* __restrict__ sv) {
    __shared__ float s[MDIM];
    const int t = threadIdx.x;
    const size_t row = blockIdx.x;
    float4* d4 = reinterpret_cast<float4*>(data + row * MDIM);
    float4 v = d4[t];
    s[4*t+0] = v.x; s[4*t+1] = v.y; s[4*t+2] = v.z; s[4*t+3] = v.w;
    __syncthreads();
    #pragma unroll
    for (int h = 1; h < MDIM; h <<= 1) {
        #pragma unroll
        for (int p = t; p < MDIM / 2; p += 1024) {
            int i = ((p & ~(h - 1)) << 1) | (p & (h - 1));
            float a = s[i], b = s[i + h];
            s[i]     = a + b;
            s[i + h] = a - b;
        }
        __syncthreads();
    }
    const float4* sv4 = reinterpret_cast<const float4*>(sv);
    float4 sc = sv4[t];
    float4 o;
    o.x = s[4*t+0] * sc.x * 0.015625f;
    o.y = s[4*t+1] * sc.y * 0.015625f;
    o.z = s[4*t+2] * sc.z * 0.015625f;
    o.w = s[4*t+3] * sc.w * 0.015625f;
    d4[t] = o;
}

// ---------------------------------------------------------------------------
// Kernel 3: C[i,j] = sum_k Xh[i,k] * W[j,k]   (NT GEMM, tf32 MMA, fp32 accum)
// Tile 128x128x32; 8 warps (2 along M x 4 along N), warp tile 64x32.
// mma.sync.m16n8k8: 4 m-tiles x 4 n-tiles per warp per k-step.
// ---------------------------------------------------------------------------
#define BKg  32
#define PADg 36   // 36 floats/row: keeps 16B alignment AND conflict-free frag reads

__global__ __launch_bounds__(256, 1)
void gemm_tf32_kernel(const float* __restrict__ A,
                      const float* __restrict__ B,
                      float*       __restrict__ C) {
    __shared__ float As[128 * PADg];
    __shared__ float Bs[128 * PADg];

    const int tid   = threadIdx.x;
    const int warpId = tid >> 5;
    const int lane  = tid & 31;
    const int g     = lane >> 2;      // 0..7
    const int t4    = lane & 3;       // 0..3
    const int wm    = (warpId & 1) * 64;   // warp M offset
    const int wn    = (warpId >> 1) * 32;  // warp N offset

    const int ldr = tid >> 3;         // 0..31  (row within 32-row chunk)
    const int ldc = (tid & 7) * 4;    // 0,4,...,28

    const float* Ag = A + (size_t)(blockIdx.y * 128 + ldr) * NDIM + ldc;
    const float* Bg = B + (size_t)(blockIdx.x * 128 + ldr) * NDIM + ldc;

    float4 ra[4], rb[4];
    float c[4][4][4];
    #pragma unroll
    for (int i = 0; i < 4; i++)
        #pragma unroll
        for (int j = 0; j < 4; j++)
            #pragma unroll
            for (int k = 0; k < 4; k++) c[i][j][k] = 0.f;

    // prologue: load k-tile 0 into smem
    #pragma unroll
    for (int i = 0; i < 4; i++) {
        ra[i] = *reinterpret_cast<const float4*>(Ag + (size_t)(i * 32) * NDIM);
        rb[i] = *reinterpret_cast<const float4*>(Bg + (size_t)(i * 32) * NDIM);
    }
    #pragma unroll
    for (int i = 0; i < 4; i++) {
        *reinterpret_cast<float4*>(&As[(ldr + i * 32) * PADg + ldc]) = ra[i];
        *reinterpret_cast<float4*>(&Bs[(ldr + i * 32) * PADg + ldc]) = rb[i];
    }
    __syncthreads();

    const int KT = NDIM / BKg;  // 128
    for (int kt = 1; kt <= KT; kt++) {
        // prefetch next tile into registers while computing current
        if (kt < KT) {
            const float* Agk = Ag + kt * BKg;
            const float* Bgk = Bg + kt * BKg;
            #pragma unroll
            for (int i = 0; i < 4; i++) {
                ra[i] = *reinterpret_cast<const float4*>(Agk + (size_t)(i * 32) * NDIM);
                rb[i] = *reinterpret_cast<const float4*>(Bgk + (size_t)(i * 32) * NDIM);
            }
        }

        #pragma unroll
        for (int ks = 0; ks < 4; ks++) {
            const int k0 = ks * 8;
            uint32_t af[4][4], bf[4][2];
            #pragma unroll
            for (int mi = 0; mi < 4; mi++) {
                const int m = wm + mi * 16;
                af[mi][0] = __float_as_uint(As[(m + g    ) * PADg + k0 + t4    ]);
                af[mi][1] = __float_as_uint(As[(m + g + 8) * PADg + k0 + t4    ]);
                af[mi][2] = __float_as_uint(As[(m + g    ) * PADg + k0 + t4 + 4]);
                af[mi][3] = __float_as_uint(As[(m + g + 8) * PADg + k0 + t4 + 4]);
            }
            #pragma unroll
            for (int ni = 0; ni < 4; ni++) {
                const int n = wn + ni * 8;
                bf[ni][0] = __float_as_uint(Bs[(n + g) * PADg + k0 + t4    ]);
                bf[ni][1] = __float_as_uint(Bs[(n + g) * PADg + k0 + t4 + 4]);
            }
            #pragma unroll
            for (int mi = 0; mi < 4; mi++)
                #pragma unroll
                for (int ni = 0; ni < 4; ni++) {
                    asm volatile(
                        "mma.sync.aligned.m16n8k8.row.col.f32.tf32.tf32.f32 "
                        "{%0,%1,%2,%3}, {%4,%5,%6,%7}, {%8,%9}, {%0,%1,%2,%3};\n"
                        : "+f"(c[mi][ni][0]), "+f"(c[mi][ni][1]),
                          "+f"(c[mi][ni][2]), "+f"(c[mi][ni][3])
                        : "r"(af[mi][0]), "r"(af[mi][1]), "r"(af[mi][2]), "r"(af[mi][3]),
                          "r"(bf[ni][0]), "r"(bf[ni][1]));
                }
        }
        __syncthreads();
        if (kt < KT) {
            #pragma unroll
            for (int i = 0; i < 4; i++) {
                *reinterpret_cast<float4*>(&As[(ldr + i * 32) * PADg + ldc]) = ra[i];
                *reinterpret_cast<float4*>(&Bs[(ldr + i * 32) * PADg + ldc]) = rb[i];
            }
            __syncthreads();
        }
    }

    // epilogue: c0,c1 -> (row g, cols 2t4,2t4+1); c2,c3 -> (row g+8, same cols)
    float* Cb = C + (size_t)(blockIdx.y * 128 + wm) * MDIM + blockIdx.x * 128 + wn;
    #pragma unroll
    for (int mi = 0; mi < 4; mi++) {
        #pragma unroll
        for (int ni = 0; ni < 4; ni++) {
            const int col = ni * 8 + 2 * t4;
            float2 v0 = make_float2(c[mi][ni][0], c[mi][ni][1]);
            float2 v1 = make_float2(c[mi][ni][2], c[mi][ni][3]);
            *reinterpret_cast<float2*>(Cb + (size_t)(mi * 16 + g    ) * MDIM + col) = v0;
            *reinterpret_cast<float2*>(Cb + (size_t)(mi * 16 + g + 8) * MDIM + col) = v1;
        }
    }
}

// ---------------------------------------------------------------------------
// Launch: input, SU, SV, grid, Qidxs (metadata order)
// ---------------------------------------------------------------------------
extern "C" void kernel_launch(void* const* d_in, const int* in_sizes, int n_in,
                              void* d_out, int out_size) {
    const float* input = (const float*)d_in[0];
    const float* SU    = (const float*)d_in[1];
    const float* SV    = (const float*)d_in[2];
    const float* grid  = (const float*)d_in[3];
    const int*   qidxs = (const int*)  d_in[4];
    float* out = (float*)d_out;

    float* Xh = nullptr;
    float* W  = nullptr;
    cudaGetSymbolAddress((void**)&Xh, g_Xh);
    cudaGetSymbolAddress((void**)&W,  g_W);

    // 1. dequantize codebook -> W (tf32-rounded)
    dequant_kernel<<<(NCODE + 255) / 256, 256>>>(grid, qidxs, W);

    // 2. Xh = tf32( FWHT(input * SU) / 64 )
    fwht_su_kernel<<<ROWS_T, 1024>>>(input, SU, Xh);

    // 3. out = Xh @ W^T  (tf32 MMA, fp32 accumulate)
    dim3 gdim(MDIM / 128, ROWS_T / 128);
    gemm_tf32_kernel<<<gdim, 256>>>(Xh, W, out);

    // 4. out = FWHT(out) * SV / 64   (in place)
    fwht_sv_kernel<<<ROWS_T, 1024>>>(out, SV);
}

// round 3
// speedup vs baseline: 1.0026x; 1.0026x over previous
#include <cuda_runtime.h>
#include <cstdint>

// Problem shape (fixed by reference): B=2, S=2048 -> ROWS=4096, n=m=4096
#define ROWS_T 4096
#define NDIM   4096
#define MDIM   4096
#define NCODE  (MDIM * (NDIM / 8))   // 2,097,152 codewords

// Scratch (allocation-free rule: __device__ globals)
__device__ float g_Xh[(size_t)ROWS_T * NDIM];   // Hadamard-rotated input (tf32-rounded)
__device__ float g_W [(size_t)MDIM   * NDIM];   // dequantized weights (tf32-rounded)

__device__ __forceinline__ float to_tf32(float x) {
    uint32_t u;
    asm("cvt.rna.tf32.f32 %0, %1;" : "=r"(u) : "f"(x));
    return __uint_as_float(u);
}

// ---------------------------------------------------------------------------
// Kernel 1: W = grid[Qidxs].reshape(m, n), rounded to tf32
// ---------------------------------------------------------------------------
__global__ void dequant_kernel(const float* __restrict__ grid,
                               const int*   __restrict__ qidxs,
                               float*       __restrict__ W) {
    int i = blockIdx.x * blockDim.x + threadIdx.x;
    if (i >= NCODE) return;
    int idx = qidxs[i];
    const float4* g4 = reinterpret_cast<const float4*>(grid) + (size_t)idx * 2;
    float4 a = g4[0], b = g4[1];
    float4 oa = make_float4(to_tf32(a.x), to_tf32(a.y), to_tf32(a.z), to_tf32(a.w));
    float4 ob = make_float4(to_tf32(b.x), to_tf32(b.y), to_tf32(b.z), to_tf32(b.w));
    float4* o4 = reinterpret_cast<float4*>(W) + (size_t)i * 2;
    o4[0] = oa; o4[1] = ob;
}

// ---------------------------------------------------------------------------
// Kernel 2: Xh[row] = tf32( FWHT(input[row] * SU) * (1/64) )
// One block per row, 1024 threads, full row in shared memory.
// ---------------------------------------------------------------------------
__global__ void fwht_su_kernel(const float* __restrict__ in,
                               const float* __restrict__ su,
                               float*       __restrict__ out) {
    __shared__ float s[NDIM];
    const int t = threadIdx.x;                 // 0..1023
    const size_t row = blockIdx.x;
    const float4* in4 = reinterpret_cast<const float4*>(in + row * NDIM);
    const float4* su4 = reinterpret_cast<const float4*>(su);
    float4 v = in4[t];
    float4 sc = su4[t];
    s[4*t+0] = v.x * sc.x;
    s[4*t+1] = v.y * sc.y;
    s[4*t+2] = v.z * sc.z;
    s[4*t+3] = v.w * sc.w;
    __syncthreads();
    #pragma unroll
    for (int h = 1; h < NDIM; h <<= 1) {
        #pragma unroll
        for (int p = t; p < NDIM / 2; p += 1024) {
            int i = ((p & ~(h - 1)) << 1) | (p & (h - 1));
            float a = s[i], b = s[i + h];
            s[i]     = a + b;
            s[i + h] = a - b;
        }
        __syncthreads();
    }
    float4 o;
    o.x = to_tf32(s[4*t+0] * 0.015625f);
    o.y = to_tf32(s[4*t+1] * 0.015625f);
    o.z = to_tf32(s[4*t+2] * 0.015625f);
    o.w = to_tf32(s[4*t+3] * 0.015625f);
    reinterpret_cast<float4*>(out + row * NDIM)[t] = o;
}

// ---------------------------------------------------------------------------
// Kernel 4: in-place row-FWHT on GEMM output, fused with SV * (1/64)
// ---------------------------------------------------------------------------
__global__ void fwht_sv_kernel(float* __restrict__ data,
                               const float* __restrict__ sv) {
    __shared__ float s[MDIM];
    const int t = threadIdx.x;
    const size_t row = blockIdx.x;
    float4* d4 = reinterpret_cast<float4*>(data + row * MDIM);
    float4 v = d4[t];
    s[4*t+0] = v.x; s[4*t+1] = v.y; s[4*t+2] = v.z; s[4*t+3] = v.w;
    __syncthreads();
    #pragma unroll
    for (int h = 1; h < MDIM; h <<= 1) {
        #pragma unroll
        for (int p = t; p < MDIM / 2; p += 1024) {
            int i = ((p & ~(h - 1)) << 1) | (p & (h - 1));
            float a = s[i], b = s[i + h];
            s[i]     = a + b;
            s[i + h] = a - b;
        }
        __syncthreads();
    }
    const float4* sv4 = reinterpret_cast<const float4*>(sv);
    float4 sc = sv4[t];
    float4 o;
    o.x = s[4*t+0] * sc.x * 0.015625f;
    o.y = s[4*t+1] * sc.y * 0.015625f;
    o.z = s[4*t+2] * sc.z * 0.015625f;
    o.w = s[4*t+3] * sc.w * 0.015625f;
    d4[t] = o;
}

// ---------------------------------------------------------------------------
// Kernel 3: C[i,j] = sum_k Xh[i,k] * W[j,k]   (NT GEMM, tf32 MMA, fp32 accum)
// Tile 128x128x32; 8 warps (2 along M x 4 along N), warp tile 64x32.
// mma.sync.m16n8k8: 4 m-tiles x 4 n-tiles per warp per k-step.
// ---------------------------------------------------------------------------
#define BKg  32
#define PADg 36   // 36 floats/row: keeps 16B alignment AND conflict-free frag reads

__global__ __launch_bounds__(256, 1)
void gemm_tf32_kernel(const float* __restrict__ A,
                      const float* __restrict__ B,
                      float*       __restrict__ C) {
    __shared__ float As[128 * PADg];
    __shared__ float Bs[128 * PADg];

    const int tid   = threadIdx.x;
    const int warpId = tid >> 5;
    const int lane  = tid & 31;
    const int g     = lane >> 2;      // 0..7
    const int t4    = lane & 3;       // 0..3
    const int wm    = (warpId & 1) * 64;   // warp M offset
    const int wn    = (warpId >> 1) * 32;  // warp N offset

    const int ldr = tid >> 3;         // 0..31  (row within 32-row chunk)
    const int ldc = (tid & 7) * 4;    // 0,4,...,28

    const float* Ag = A + (size_t)(blockIdx.y * 128 + ldr) * NDIM + ldc;
    const float* Bg = B + (size_t)(blockIdx.x * 128 + ldr) * NDIM + ldc;

    float4 ra[4], rb[4];
    float c[4][4][4];
    #pragma unroll
    for (int i = 0; i < 4; i++)
        #pragma unroll
        for (int j = 0; j < 4; j++)
            #pragma unroll
            for (int k = 0; k < 4; k++) c[i][j][k] = 0.f;

    // prologue: load k-tile 0 into smem
    #pragma unroll
    for (int i = 0; i < 4; i++) {
        ra[i] = *reinterpret_cast<const float4*>(Ag + (size_t)(i * 32) * NDIM);
        rb[i] = *reinterpret_cast<const float4*>(Bg + (size_t)(i * 32) * NDIM);
    }
    #pragma unroll
    for (int i = 0; i < 4; i++) {
        *reinterpret_cast<float4*>(&As[(ldr + i * 32) * PADg + ldc]) = ra[i];
        *reinterpret_cast<float4*>(&Bs[(ldr + i * 32) * PADg + ldc]) = rb[i];
    }
    __syncthreads();

    const int KT = NDIM / BKg;  // 128
    for (int kt = 1; kt <= KT; kt++) {
        // prefetch next tile into registers while computing current
        if (kt < KT) {
            const float* Agk = Ag + kt * BKg;
            const float* Bgk = Bg + kt * BKg;
            #pragma unroll
            for (int i = 0; i < 4; i++) {
                ra[i] = *reinterpret_cast<const float4*>(Agk + (size_t)(i * 32) * NDIM);
                rb[i] = *reinterpret_cast<const float4*>(Bgk + (size_t)(i * 32) * NDIM);
            }
        }

        #pragma unroll
        for (int ks = 0; ks < 4; ks++) {
            const int k0 = ks * 8;
            uint32_t af[4][4], bf[4][2];
            #pragma unroll
            for (int mi = 0; mi < 4; mi++) {
                const int m = wm + mi * 16;
                af[mi][0] = __float_as_uint(As[(m + g    ) * PADg + k0 + t4    ]);
                af[mi][1] = __float_as_uint(As[(m + g + 8) * PADg + k0 + t4    ]);
                af[mi][2] = __float_as_uint(As[(m + g    ) * PADg + k0 + t4 + 4]);
                af[mi][3] = __float_as_uint(As[(m + g + 8) * PADg + k0 + t4 + 4]);
            }
            #pragma unroll
            for (int ni = 0; ni < 4; ni++) {
                const int n = wn + ni * 8;
                bf[ni][0] = __float_as_uint(Bs[(n + g) * PADg + k0 + t4    ]);
                bf[ni][1] = __float_as_uint(Bs[(n + g) * PADg + k0 + t4 + 4]);
            }
            #pragma unroll
            for (int mi = 0; mi < 4; mi++)
                #pragma unroll
                for (int ni = 0; ni < 4; ni++) {
                    asm volatile(
                        "mma.sync.aligned.m16n8k8.row.col.f32.tf32.tf32.f32 "
                        "{%0,%1,%2,%3}, {%4,%5,%6,%7}, {%8,%9}, {%0,%1,%2,%3};\n"
                        : "+f"(c[mi][ni][0]), "+f"(c[mi][ni][1]),
                          "+f"(c[mi][ni][2]), "+f"(c[mi][ni][3])
                        : "r"(af[mi][0]), "r"(af[mi][1]), "r"(af[mi][2]), "r"(af[mi][3]),
                          "r"(bf[ni][0]), "r"(bf[ni][1]));
                }
        }
        __syncthreads();
        if (kt < KT) {
            #pragma unroll
            for (int i = 0; i < 4; i++) {
                *reinterpret_cast<float4*>(&As[(ldr + i * 32) * PADg + ldc]) = ra[i];
                *reinterpret_cast<float4*>(&Bs[(ldr + i * 32) * PADg + ldc]) = rb[i];
            }
            __syncthreads();
        }
    }

    // epilogue: c0,c1 -> (row g, cols 2t4,2t4+1); c2,c3 -> (row g+8, same cols)
    float* Cb = C + (size_t)(blockIdx.y * 128 + wm) * MDIM + blockIdx.x * 128 + wn;
    #pragma unroll
    for (int mi = 0; mi < 4; mi++) {
        #pragma unroll
        for (int ni = 0; ni < 4; ni++) {
            const int col = ni * 8 + 2 * t4;
            float2 v0 = make_float2(c[mi][ni][0], c[mi][ni][1]);
            float2 v1 = make_float2(c[mi][ni][2], c[mi][ni][3]);
            *reinterpret_cast<float2*>(Cb + (size_t)(mi * 16 + g    ) * MDIM + col) = v0;
            *reinterpret_cast<float2*>(Cb + (size_t)(mi * 16 + g + 8) * MDIM + col) = v1;
        }
    }
}

// ---------------------------------------------------------------------------
// Launch: input, SU, SV, grid, Qidxs (metadata order)
// ---------------------------------------------------------------------------
extern "C" void kernel_launch(void* const* d_in, const int* in_sizes, int n_in,
                              void* d_out, int out_size) {
    const float* input = (const float*)d_in[0];
    const float* SU    = (const float*)d_in[1];
    const float* SV    = (const float*)d_in[2];
    const float* grid  = (const float*)d_in[3];
    const int*   qidxs = (const int*)  d_in[4];
    float* out = (float*)d_out;

    float* Xh = nullptr;
    float* W  = nullptr;
    cudaGetSymbolAddress((void**)&Xh, g_Xh);
    cudaGetSymbolAddress((void**)&W,  g_W);

    // 1. dequantize codebook -> W (tf32-rounded)
    dequant_kernel<<<(NCODE + 255) / 256, 256>>>(grid, qidxs, W);

    // 2. Xh = tf32( FWHT(input * SU) / 64 )
    fwht_su_kernel<<<ROWS_T, 1024>>>(input, SU, Xh);

    // 3. out = Xh @ W^T  (tf32 MMA, fp32 accumulate)
    dim3 gdim(MDIM / 128, ROWS_T / 128);
    gemm_tf32_kernel<<<gdim, 256>>>(Xh, W, out);

    // 4. out = FWHT(out) * SV / 64   (in place)
    fwht_sv_kernel<<<ROWS_T, 1024>>>(out, SV);
}

// round 6
// speedup vs baseline: 2.4921x; 2.4857x over previous
#include <cuda_runtime.h>
#include <cuda_fp16.h>
#include <cstdint>

// Problem shape (fixed): B=2, S=2048 -> ROWS=4096, n=m=4096
#define ROWS_T 4096
#define NDIM   4096
#define MDIM   4096
#define NCODE  (MDIM * (NDIM / 8))   // 2,097,152 codewords

// Scratch (allocation-free rule: __device__ globals)
__device__ __half g_Xh[(size_t)ROWS_T * NDIM];   // fp16 Hadamard-rotated input
__device__ __half g_W [(size_t)MDIM   * NDIM];   // fp16 dequantized weights

// ===========================================================================
// helpers
// ===========================================================================
__device__ __forceinline__ uint32_t smem_u32(const void* p) {
    uint32_t a;
    asm("{ .reg .u64 t; cvta.to.shared.u64 t, %1; cvt.u32.u64 %0, t; }" : "=r"(a) : "l"(p));
    return a;
}
__device__ __forceinline__ void cp_async16(uint32_t dst, const void* src) {
    asm volatile("cp.async.cg.shared.global [%0], [%1], 16;\n" :: "r"(dst), "l"(src));
}
#define CP_COMMIT() asm volatile("cp.async.commit_group;\n")
#define CP_WAIT2()  asm volatile("cp.async.wait_group 2;\n" ::: "memory")

// SW128 swizzle of a byte offset within a tile (rows of 128B)
#define SWZ(b) ((b) ^ (((b) >> 3) & 0x70))

#define LDSM4(r0, r1, r2, r3, addr) \
    asm volatile("ldmatrix.sync.aligned.m8n8.x4.shared.b16 {%0,%1,%2,%3}, [%4];" \
        : "=r"(r0), "=r"(r1), "=r"(r2), "=r"(r3) : "r"(addr))

#define MMA16816(d, a, b0, b1) \
    asm volatile("mma.sync.aligned.m16n8k16.row.col.f32.f16.f16.f32 " \
        "{%0,%1,%2,%3}, {%4,%5,%6,%7}, {%8,%9}, {%0,%1,%2,%3};" \
        : "+f"((d)[0]), "+f"((d)[1]), "+f"((d)[2]), "+f"((d)[3]) \
        : "r"((a)[0]), "r"((a)[1]), "r"((a)[2]), "r"((a)[3]), "r"(b0), "r"(b1))

// ===========================================================================
// Kernel 1: W = fp16( grid[Qidxs].reshape(m, n) )
// ===========================================================================
__global__ void dequant_kernel(const float* __restrict__ grid,
                               const int*   __restrict__ qidxs,
                               __half*      __restrict__ W) {
    int i = blockIdx.x * blockDim.x + threadIdx.x;
    if (i >= NCODE) return;
    int idx = qidxs[i];
    const float4* g4 = reinterpret_cast<const float4*>(grid) + (size_t)idx * 2;
    float4 a = g4[0], b = g4[1];
    __half2 h0 = __floats2half2_rn(a.x, a.y);
    __half2 h1 = __floats2half2_rn(a.z, a.w);
    __half2 h2 = __floats2half2_rn(b.x, b.y);
    __half2 h3 = __floats2half2_rn(b.z, b.w);
    uint4 o;
    o.x = *reinterpret_cast<uint32_t*>(&h0);
    o.y = *reinterpret_cast<uint32_t*>(&h1);
    o.z = *reinterpret_cast<uint32_t*>(&h2);
    o.w = *reinterpret_cast<uint32_t*>(&h3);
    reinterpret_cast<uint4*>(W)[i] = o;
}

// ===========================================================================
// FWHT, 3-pass radix-16: 256 threads, 16 elems/thread in registers.
// Padded smem phys(e) = e + (e>>4) -> conflict-free for all 3 passes.
// ===========================================================================
__device__ __forceinline__ void fwht16(float v[16]) {
    #pragma unroll
    for (int h = 1; h < 16; h <<= 1) {
        #pragma unroll
        for (int j = 0; j < 16; j += 2 * h) {
            #pragma unroll
            for (int k = 0; k < h; k++) {
                float a = v[j + k], b = v[j + k + h];
                v[j + k]     = a + b;
                v[j + k + h] = a - b;
            }
        }
    }
}

__global__ __launch_bounds__(256)
void fwht_su_kernel(const float* __restrict__ in,
                    const float* __restrict__ su,
                    __half*      __restrict__ out) {
    __shared__ float s[4096 + 256];
    const int t = threadIdx.x;
    const size_t row = blockIdx.x;
    float v[16];
    const float4* in4 = reinterpret_cast<const float4*>(in + row * NDIM) + t * 4;
    const float4* su4 = reinterpret_cast<const float4*>(su) + t * 4;
    #pragma unroll
    for (int i = 0; i < 4; i++) {
        float4 a = in4[i], b = su4[i];
        v[4*i+0] = a.x * b.x; v[4*i+1] = a.y * b.y;
        v[4*i+2] = a.z * b.z; v[4*i+3] = a.w * b.w;
    }
    fwht16(v);                                   // bits 0-3
    #pragma unroll
    for (int i = 0; i < 16; i++) s[17 * t + i] = v[i];
    __syncthreads();
    const int r = t & 15, q = t >> 4;
    const int b2 = 272 * q + r;
    #pragma unroll
    for (int i = 0; i < 16; i++) v[i] = s[b2 + 17 * i];
    fwht16(v);                                   // bits 4-7
    #pragma unroll
    for (int i = 0; i < 16; i++) s[b2 + 17 * i] = v[i];
    __syncthreads();
    const int b3 = t + (t >> 4);
    #pragma unroll
    for (int i = 0; i < 16; i++) v[i] = s[b3 + 272 * i];
    fwht16(v);                                   // bits 8-11
    __half* o = out + row * NDIM + t;
    #pragma unroll
    for (int i = 0; i < 16; i++) o[256 * i] = __float2half_rn(v[i] * 0.015625f);
}

__global__ __launch_bounds__(256)
void fwht_sv_kernel(float* __restrict__ data, const float* __restrict__ sv) {
    __shared__ float s[4096 + 256];
    const int t = threadIdx.x;
    const size_t row = blockIdx.x;
    float v[16];
    const float4* d4 = reinterpret_cast<const float4*>(data + row * MDIM) + t * 4;
    #pragma unroll
    for (int i = 0; i < 4; i++) {
        float4 a = d4[i];
        v[4*i+0] = a.x; v[4*i+1] = a.y; v[4*i+2] = a.z; v[4*i+3] = a.w;
    }
    fwht16(v);
    #pragma unroll
    for (int i = 0; i < 16; i++) s[17 * t + i] = v[i];
    __syncthreads();
    const int r = t & 15, q = t >> 4;
    const int b2 = 272 * q + r;
    #pragma unroll
    for (int i = 0; i < 16; i++) v[i] = s[b2 + 17 * i];
    fwht16(v);
    #pragma unroll
    for (int i = 0; i < 16; i++) s[b2 + 17 * i] = v[i];
    __syncthreads();
    const int b3 = t + (t >> 4);
    #pragma unroll
    for (int i = 0; i < 16; i++) v[i] = s[b3 + 272 * i];
    fwht16(v);
    float* o = data + row * MDIM + t;
    const float* svp = sv + t;
    #pragma unroll
    for (int i = 0; i < 16; i++) o[256 * i] = v[i] * svp[256 * i] * 0.015625f;
}

// ===========================================================================
// Kernel 3: fp16 mma.sync GEMM  C[4096,4096] = A @ B^T (both K-major fp16)
// CTA tile 128x128x64(halves); 8 warps (2M x 4N), warp tile 64x32.
// SW128-swizzled smem, cp.async 4-stage pipeline, ldmatrix.x4 frag loads.
// ===========================================================================
#define NST      4
#define A_ST     (128 * 128)          // bytes per A stage (128 rows x 128B)
#define B_ST     (128 * 128)
#define STG      (A_ST + B_ST)        // 32 KB
#define GEMM_SMEM (NST * STG + 1024)

__device__ __forceinline__ void load_stage(uint32_t s0, int st, int kt, int tid,
                                           const __half* Ab, const __half* Bb) {
    uint32_t sA = s0 + st * STG;
    uint32_t sB = sA + A_ST;
    #pragma unroll
    for (int it = 0; it < 8; it++) {
        int c = tid + it * 256;                  // 0..2047
        if (c < 1024) {                          // A: 128 rows x 8 chunks(16B)
            int rr = c >> 3, cc = c & 7;
            cp_async16(sA + SWZ(rr * 128 + cc * 16),
                       Ab + (size_t)rr * NDIM + kt * 64 + cc * 8);
        } else {                                 // B
            int b = c - 1024;
            int rr = b >> 3, cc = b & 7;
            cp_async16(sB + SWZ(rr * 128 + cc * 16),
                       Bb + (size_t)rr * NDIM + kt * 64 + cc * 8);
        }
    }
    CP_COMMIT();
}

__global__ __launch_bounds__(256, 1)
void gemm_fp16(const __half* __restrict__ A,
               const __half* __restrict__ B,
               float*        __restrict__ C) {
    extern __shared__ char smraw[];
    const uint32_t s0 = (smem_u32(smraw) + 1023u) & ~1023u;
    const int tid  = threadIdx.x;
    const int wid  = tid >> 5;
    const int lane = tid & 31;
    const int g    = lane >> 2;
    const int t4   = lane & 3;
    const int wm   = (wid & 1) * 64;
    const int wn   = (wid >> 1) * 32;

    // ldmatrix lane-address selectors
    const int a_row = (lane & 7) + ((lane & 8)  ? 8 : 0);   // blocks: m0-7,m8-15 x k0,k8
    const int a_kx  = (lane & 16) ? 16 : 0;
    const int b_row = (lane & 7) + ((lane & 16) ? 8 : 0);   // blocks: n0-7 k0,k8; n8-15 k0,k8
    const int b_kx  = (lane & 8)  ? 16 : 0;

    const __half* Ab = A + (size_t)(blockIdx.y * 128) * NDIM;
    const __half* Bb = B + (size_t)(blockIdx.x * 128) * NDIM;

    float c[4][4][4];
    #pragma unroll
    for (int i = 0; i < 4; i++)
        #pragma unroll
        for (int j = 0; j < 4; j++)
            #pragma unroll
            for (int k = 0; k < 4; k++) c[i][j][k] = 0.f;

    #pragma unroll
    for (int s = 0; s < NST - 1; s++) load_stage(s0, s, s, tid, Ab, Bb);

    const int KT = NDIM / 64;   // 64 k-tiles
    for (int kt = 0; kt < KT; kt++) {
        const int st = kt & (NST - 1);
        CP_WAIT2();
        __syncthreads();
        if (kt + NST - 1 < KT)
            load_stage(s0, (kt + NST - 1) & (NST - 1), kt + NST - 1, tid, Ab, Bb);

        const uint32_t sA = s0 + st * STG;
        const uint32_t sB = sA + A_ST;
        #pragma unroll
        for (int ks = 0; ks < 4; ks++) {
            const int kb_a = ks * 32 + a_kx;
            const int kb_b = ks * 32 + b_kx;
            uint32_t af[4][4], bf[4][2];
            #pragma unroll
            for (int mi = 0; mi < 4; mi++) {
                int row = wm + mi * 16 + a_row;
                uint32_t ad = sA + row * 128 + (kb_a ^ ((row & 7) << 4));
                LDSM4(af[mi][0], af[mi][1], af[mi][2], af[mi][3], ad);
            }
            #pragma unroll
            for (int nb = 0; nb < 2; nb++) {
                int row = wn + nb * 16 + b_row;
                uint32_t bd = sB + row * 128 + (kb_b ^ ((row & 7) << 4));
                LDSM4(bf[2*nb][0], bf[2*nb][1], bf[2*nb+1][0], bf[2*nb+1][1], bd);
            }
            #pragma unroll
            for (int mi = 0; mi < 4; mi++)
                #pragma unroll
                for (int ni = 0; ni < 4; ni++)
                    MMA16816(c[mi][ni], af[mi], bf[ni][0], bf[ni][1]);
        }
        __syncthreads();
    }

    // epilogue: c0,c1 -> (row g, cols 2t4,2t4+1); c2,c3 -> (row g+8)
    float* Cb = C + (size_t)(blockIdx.y * 128 + wm) * MDIM + blockIdx.x * 128 + wn;
    #pragma unroll
    for (int mi = 0; mi < 4; mi++) {
        #pragma unroll
        for (int ni = 0; ni < 4; ni++) {
            const int col = ni * 8 + 2 * t4;
            *reinterpret_cast<float2*>(Cb + (size_t)(mi * 16 + g    ) * MDIM + col) =
                make_float2(c[mi][ni][0], c[mi][ni][1]);
            *reinterpret_cast<float2*>(Cb + (size_t)(mi * 16 + g + 8) * MDIM + col) =
                make_float2(c[mi][ni][2], c[mi][ni][3]);
        }
    }
}

// ===========================================================================
// Launch: input, SU, SV, grid, Qidxs (metadata order)
// ===========================================================================
extern "C" void kernel_launch(void* const* d_in, const int* in_sizes, int n_in,
                              void* d_out, int out_size) {
    const float* input = (const float*)d_in[0];
    const float* SU    = (const float*)d_in[1];
    const float* SV    = (const float*)d_in[2];
    const float* grid  = (const float*)d_in[3];
    const int*   qidxs = (const int*)  d_in[4];
    float* out = (float*)d_out;

    __half* Xh = nullptr;
    __half* W  = nullptr;
    cudaGetSymbolAddress((void**)&Xh, g_Xh);
    cudaGetSymbolAddress((void**)&W,  g_W);

    cudaFuncSetAttribute(gemm_fp16, cudaFuncAttributeMaxDynamicSharedMemorySize, GEMM_SMEM);

    // 1. dequantize codebook -> W (fp16)
    dequant_kernel<<<(NCODE + 255) / 256, 256>>>(grid, qidxs, W);

    // 2. Xh = fp16( FWHT(input * SU) / 64 )
    fwht_su_kernel<<<ROWS_T, 256>>>(input, SU, Xh);

    // 3. out = Xh @ W^T  (fp16 mma.sync, fp32 accumulate)
    dim3 gdim(MDIM / 128, ROWS_T / 128);
    gemm_fp16<<<gdim, 256, GEMM_SMEM>>>(Xh, W, out);

    // 4. out = FWHT(out) * SV / 64   (in place)
    fwht_sv_kernel<<<ROWS_T, 256>>>(out, SV);
}

// round 7
// speedup vs baseline: 2.6306x; 1.0556x over previous
#include <cuda_runtime.h>
#include <cuda_fp16.h>
#include <cstdint>

// Problem shape (fixed): B=2, S=2048 -> ROWS=4096, n=m=4096
#define ROWS_T 4096
#define NDIM   4096
#define MDIM   4096
#define NCODE  (MDIM * (NDIM / 8))   // 2,097,152 codewords

// Scratch (allocation-free rule: __device__ globals)
__device__ __half g_Xh[(size_t)ROWS_T * NDIM];   // fp16 Hadamard-rotated input
__device__ __half g_W [(size_t)MDIM   * NDIM];   // fp16 dequantized weights

// ===========================================================================
// helpers
// ===========================================================================
__device__ __forceinline__ uint32_t smem_u32(const void* p) {
    uint32_t a;
    asm("{ .reg .u64 t; cvta.to.shared.u64 t, %1; cvt.u32.u64 %0, t; }" : "=r"(a) : "l"(p));
    return a;
}
__device__ __forceinline__ void cp_async16(uint32_t dst, const void* src) {
    asm volatile("cp.async.cg.shared.global [%0], [%1], 16;\n" :: "r"(dst), "l"(src));
}
#define CP_COMMIT() asm volatile("cp.async.commit_group;\n")
#define CP_WAIT1()  asm volatile("cp.async.wait_group 1;\n" ::: "memory")

// SW128 swizzle of a byte offset within a tile (rows of 128B)
#define SWZ(b) ((b) ^ (((b) >> 3) & 0x70))

#define LDSM4(r0, r1, r2, r3, addr) \
    asm volatile("ldmatrix.sync.aligned.m8n8.x4.shared.b16 {%0,%1,%2,%3}, [%4];" \
        : "=r"(r0), "=r"(r1), "=r"(r2), "=r"(r3) : "r"(addr))

#define MMA16816(d, a, b0, b1) \
    asm volatile("mma.sync.aligned.m16n8k16.row.col.f32.f16.f16.f32 " \
        "{%0,%1,%2,%3}, {%4,%5,%6,%7}, {%8,%9}, {%0,%1,%2,%3};" \
        : "+f"((d)[0]), "+f"((d)[1]), "+f"((d)[2]), "+f"((d)[3]) \
        : "r"((a)[0]), "r"((a)[1]), "r"((a)[2]), "r"((a)[3]), "r"(b0), "r"(b1))

// ===========================================================================
// Kernel 1: W = fp16( grid[Qidxs].reshape(m, n) )
// ===========================================================================
__global__ void dequant_kernel(const float* __restrict__ grid,
                               const int*   __restrict__ qidxs,
                               __half*      __restrict__ W) {
    int i = blockIdx.x * blockDim.x + threadIdx.x;
    if (i >= NCODE) return;
    int idx = qidxs[i];
    const float4* g4 = reinterpret_cast<const float4*>(grid) + (size_t)idx * 2;
    float4 a = g4[0], b = g4[1];
    __half2 h0 = __floats2half2_rn(a.x, a.y);
    __half2 h1 = __floats2half2_rn(a.z, a.w);
    __half2 h2 = __floats2half2_rn(b.x, b.y);
    __half2 h3 = __floats2half2_rn(b.z, b.w);
    uint4 o;
    o.x = *reinterpret_cast<uint32_t*>(&h0);
    o.y = *reinterpret_cast<uint32_t*>(&h1);
    o.z = *reinterpret_cast<uint32_t*>(&h2);
    o.w = *reinterpret_cast<uint32_t*>(&h3);
    reinterpret_cast<uint4*>(W)[i] = o;
}

// ===========================================================================
// FWHT, 3-pass radix-16: 256 threads, 16 elems/thread in registers.
// Padded smem phys(e) = e + (e>>4) -> conflict-free for all 3 passes.
// ===========================================================================
__device__ __forceinline__ void fwht16(float v[16]) {
    #pragma unroll
    for (int h = 1; h < 16; h <<= 1) {
        #pragma unroll
        for (int j = 0; j < 16; j += 2 * h) {
            #pragma unroll
            for (int k = 0; k < h; k++) {
                float a = v[j + k], b = v[j + k + h];
                v[j + k]     = a + b;
                v[j + k + h] = a - b;
            }
        }
    }
}

__global__ __launch_bounds__(256)
void fwht_su_kernel(const float* __restrict__ in,
                    const float* __restrict__ su,
                    __half*      __restrict__ out) {
    __shared__ float s[4096 + 256];
    const int t = threadIdx.x;
    const size_t row = blockIdx.x;
    float v[16];
    const float4* in4 = reinterpret_cast<const float4*>(in + row * NDIM) + t * 4;
    const float4* su4 = reinterpret_cast<const float4*>(su) + t * 4;
    #pragma unroll
    for (int i = 0; i < 4; i++) {
        float4 a = in4[i], b = su4[i];
        v[4*i+0] = a.x * b.x; v[4*i+1] = a.y * b.y;
        v[4*i+2] = a.z * b.z; v[4*i+3] = a.w * b.w;
    }
    fwht16(v);                                   // bits 0-3
    #pragma unroll
    for (int i = 0; i < 16; i++) s[17 * t + i] = v[i];
    __syncthreads();
    const int r = t & 15, q = t >> 4;
    const int b2 = 272 * q + r;
    #pragma unroll
    for (int i = 0; i < 16; i++) v[i] = s[b2 + 17 * i];
    fwht16(v);                                   // bits 4-7
    #pragma unroll
    for (int i = 0; i < 16; i++) s[b2 + 17 * i] = v[i];
    __syncthreads();
    const int b3 = t + (t >> 4);
    #pragma unroll
    for (int i = 0; i < 16; i++) v[i] = s[b3 + 272 * i];
    fwht16(v);                                   // bits 8-11
    __half* o = out + row * NDIM + t;
    #pragma unroll
    for (int i = 0; i < 16; i++) o[256 * i] = __float2half_rn(v[i] * 0.015625f);
}

__global__ __launch_bounds__(256)
void fwht_sv_kernel(float* __restrict__ data, const float* __restrict__ sv) {
    __shared__ float s[4096 + 256];
    const int t = threadIdx.x;
    const size_t row = blockIdx.x;
    float v[16];
    const float4* d4 = reinterpret_cast<const float4*>(data + row * MDIM) + t * 4;
    #pragma unroll
    for (int i = 0; i < 4; i++) {
        float4 a = d4[i];
        v[4*i+0] = a.x; v[4*i+1] = a.y; v[4*i+2] = a.z; v[4*i+3] = a.w;
    }
    fwht16(v);
    #pragma unroll
    for (int i = 0; i < 16; i++) s[17 * t + i] = v[i];
    __syncthreads();
    const int r = t & 15, q = t >> 4;
    const int b2 = 272 * q + r;
    #pragma unroll
    for (int i = 0; i < 16; i++) v[i] = s[b2 + 17 * i];
    fwht16(v);
    #pragma unroll
    for (int i = 0; i < 16; i++) s[b2 + 17 * i] = v[i];
    __syncthreads();
    const int b3 = t + (t >> 4);
    #pragma unroll
    for (int i = 0; i < 16; i++) v[i] = s[b3 + 272 * i];
    fwht16(v);
    float* o = data + row * MDIM + t;
    const float* svp = sv + t;
    #pragma unroll
    for (int i = 0; i < 16; i++) o[256 * i] = v[i] * svp[256 * i] * 0.015625f;
}

// ===========================================================================
// Kernel 3: fp16 mma.sync GEMM  C[4096,4096] = A @ B^T (both K-major fp16)
// CTA tile 128x128x64(halves); 4 warps (2M x 2N), warp tile 64x64.
// SW128 smem, cp.async 3-stage pipeline, double-buffered ldmatrix fragments.
// ===========================================================================
#define NST      3
#define A_ST     (128 * 128)          // bytes per A stage
#define B_ST     (128 * 128)
#define STG      (A_ST + B_ST)        // 32 KB
#define GEMM_SMEM (NST * STG + 1024)  // 97 KB

__device__ __forceinline__ void load_stage(uint32_t s0, int st, int kt, int tid,
                                           const __half* Ab, const __half* Bb) {
    uint32_t sA = s0 + st * STG;
    uint32_t sB = sA + A_ST;
    #pragma unroll
    for (int it = 0; it < 16; it++) {
        int c = tid + it * 128;                  // 0..2047
        if (c < 1024) {                          // A: 128 rows x 8 chunks(16B)
            int rr = c >> 3, cc = c & 7;
            cp_async16(sA + SWZ(rr * 128 + cc * 16),
                       Ab + (size_t)rr * NDIM + kt * 64 + cc * 8);
        } else {                                 // B
            int b = c - 1024;
            int rr = b >> 3, cc = b & 7;
            cp_async16(sB + SWZ(rr * 128 + cc * 16),
                       Bb + (size_t)rr * NDIM + kt * 64 + cc * 8);
        }
    }
    CP_COMMIT();
}

__global__ __launch_bounds__(128, 2)
void gemm_fp16(const __half* __restrict__ A,
               const __half* __restrict__ B,
               float*        __restrict__ C) {
    extern __shared__ char smraw[];
    const uint32_t s0 = (smem_u32(smraw) + 1023u) & ~1023u;
    const int tid  = threadIdx.x;
    const int wid  = tid >> 5;
    const int lane = tid & 31;
    const int g    = lane >> 2;
    const int t4   = lane & 3;
    const int wm   = (wid & 1) * 64;
    const int wn   = (wid >> 1) * 64;

    // ldmatrix lane-address selectors (validated in round 6)
    const int a_row = (lane & 7) + ((lane & 8)  ? 8 : 0);
    const int a_kx  = (lane & 16) ? 16 : 0;
    const int b_row = (lane & 7) + ((lane & 16) ? 8 : 0);
    const int b_kx  = (lane & 8)  ? 16 : 0;

    const __half* Ab = A + (size_t)(blockIdx.y * 128) * NDIM;
    const __half* Bb = B + (size_t)(blockIdx.x * 128) * NDIM;

    float c[4][8][4];
    #pragma unroll
    for (int i = 0; i < 4; i++)
        #pragma unroll
        for (int j = 0; j < 8; j++)
            #pragma unroll
            for (int k = 0; k < 4; k++) c[i][j][k] = 0.f;

    // prologue: stages 0,1
    load_stage(s0, 0, 0, tid, Ab, Bb);
    load_stage(s0, 1, 1, tid, Ab, Bb);

    uint32_t af[2][4][4], bf[2][8][2];

    const int KT = NDIM / 64;   // 64 k-tiles
    for (int kt = 0; kt < KT; kt++) {
        const int st = kt % NST;
        CP_WAIT1();
        __syncthreads();
        if (kt + 2 < KT)
            load_stage(s0, (kt + 2) % NST, kt + 2, tid, Ab, Bb);

        const uint32_t sA = s0 + st * STG;
        const uint32_t sB = sA + A_ST;

        // load ks=0 fragments into buffer 0
        #pragma unroll
        for (int mi = 0; mi < 4; mi++) {
            int row = wm + mi * 16 + a_row;
            uint32_t ad = sA + row * 128 + ((a_kx) ^ ((row & 7) << 4));
            LDSM4(af[0][mi][0], af[0][mi][1], af[0][mi][2], af[0][mi][3], ad);
        }
        #pragma unroll
        for (int nb = 0; nb < 4; nb++) {
            int row = wn + nb * 16 + b_row;
            uint32_t bd = sB + row * 128 + ((b_kx) ^ ((row & 7) << 4));
            LDSM4(bf[0][2*nb][0], bf[0][2*nb][1], bf[0][2*nb+1][0], bf[0][2*nb+1][1], bd);
        }

        #pragma unroll
        for (int ks = 0; ks < 4; ks++) {
            const int cur = ks & 1, nxt = cur ^ 1;
            if (ks < 3) {   // prefetch fragments for ks+1
                const int kb_a = (ks + 1) * 32 + a_kx;
                const int kb_b = (ks + 1) * 32 + b_kx;
                #pragma unroll
                for (int mi = 0; mi < 4; mi++) {
                    int row = wm + mi * 16 + a_row;
                    uint32_t ad = sA + row * 128 + (kb_a ^ ((row & 7) << 4));
                    LDSM4(af[nxt][mi][0], af[nxt][mi][1], af[nxt][mi][2], af[nxt][mi][3], ad);
                }
                #pragma unroll
                for (int nb = 0; nb < 4; nb++) {
                    int row = wn + nb * 16 + b_row;
                    uint32_t bd = sB + row * 128 + (kb_b ^ ((row & 7) << 4));
                    LDSM4(bf[nxt][2*nb][0], bf[nxt][2*nb][1],
                          bf[nxt][2*nb+1][0], bf[nxt][2*nb+1][1], bd);
                }
            }
            #pragma unroll
            for (int mi = 0; mi < 4; mi++)
                #pragma unroll
                for (int ni = 0; ni < 8; ni++)
                    MMA16816(c[mi][ni], af[cur][mi], bf[cur][ni][0], bf[cur][ni][1]);
        }
        __syncthreads();
    }

    // epilogue
    float* Cb = C + (size_t)(blockIdx.y * 128 + wm) * MDIM + blockIdx.x * 128 + wn;
    #pragma unroll
    for (int mi = 0; mi < 4; mi++) {
        #pragma unroll
        for (int ni = 0; ni < 8; ni++) {
            const int col = ni * 8 + 2 * t4;
            *reinterpret_cast<float2*>(Cb + (size_t)(mi * 16 + g    ) * MDIM + col) =
                make_float2(c[mi][ni][0], c[mi][ni][1]);
            *reinterpret_cast<float2*>(Cb + (size_t)(mi * 16 + g + 8) * MDIM + col) =
                make_float2(c[mi][ni][2], c[mi][ni][3]);
        }
    }
}

// ===========================================================================
// Launch: input, SU, SV, grid, Qidxs (metadata order)
// ===========================================================================
extern "C" void kernel_launch(void* const* d_in, const int* in_sizes, int n_in,
                              void* d_out, int out_size) {
    const float* input = (const float*)d_in[0];
    const float* SU    = (const float*)d_in[1];
    const float* SV    = (const float*)d_in[2];
    const float* grid  = (const float*)d_in[3];
    const int*   qidxs = (const int*)  d_in[4];
    float* out = (float*)d_out;

    __half* Xh = nullptr;
    __half* W  = nullptr;
    cudaGetSymbolAddress((void**)&Xh, g_Xh);
    cudaGetSymbolAddress((void**)&W,  g_W);

    cudaFuncSetAttribute(gemm_fp16, cudaFuncAttributeMaxDynamicSharedMemorySize, GEMM_SMEM);

    // 1. dequantize codebook -> W (fp16)
    dequant_kernel<<<(NCODE + 255) / 256, 256>>>(grid, qidxs, W);

    // 2. Xh = fp16( FWHT(input * SU) / 64 )
    fwht_su_kernel<<<ROWS_T, 256>>>(input, SU, Xh);

    // 3. out = Xh @ W^T  (fp16 mma.sync, fp32 accumulate)
    dim3 gdim(MDIM / 128, ROWS_T / 128);
    gemm_fp16<<<gdim, 128, GEMM_SMEM>>>(Xh, W, out);

    // 4. out = FWHT(out) * SV / 64   (in place)
    fwht_sv_kernel<<<ROWS_T, 256>>>(out, SV);
}

// round 8
// speedup vs baseline: 3.1294x; 1.1896x over previous
#include <cuda_runtime.h>
#include <cuda_fp16.h>
#include <cstdint>

// Problem shape (fixed): B=2, S=2048 -> ROWS=4096, n=m=4096
#define ROWS_T 4096
#define NDIM   4096
#define MDIM   4096
#define NCODE  (MDIM * (NDIM / 8))   // 2,097,152 codewords

// Scratch (allocation-free rule: __device__ globals)
__device__ __half g_Xh[(size_t)ROWS_T * NDIM];   // fp16 Hadamard-rotated input
__device__ __half g_W [(size_t)MDIM   * NDIM];   // fp16 dequantized weights

// ===========================================================================
// helpers
// ===========================================================================
__device__ __forceinline__ uint32_t smem_u32(const void* p) {
    uint32_t a;
    asm("{ .reg .u64 t; cvta.to.shared.u64 t, %1; cvt.u32.u64 %0, t; }" : "=r"(a) : "l"(p));
    return a;
}
__device__ __forceinline__ void cp_async16(uint32_t dst, const void* src) {
    asm volatile("cp.async.cg.shared.global [%0], [%1], 16;\n" :: "r"(dst), "l"(src));
}
#define CP_COMMIT() asm volatile("cp.async.commit_group;\n")
#define CP_WAIT1()  asm volatile("cp.async.wait_group 1;\n" ::: "memory")

// SW128 swizzle of a byte offset within a tile (rows of 128B)
#define SWZ(b) ((b) ^ (((b) >> 3) & 0x70))

#define LDSM4(r0, r1, r2, r3, addr) \
    asm volatile("ldmatrix.sync.aligned.m8n8.x4.shared.b16 {%0,%1,%2,%3}, [%4];" \
        : "=r"(r0), "=r"(r1), "=r"(r2), "=r"(r3) : "r"(addr))

#define MMA16816(d, a, b0, b1) \
    asm volatile("mma.sync.aligned.m16n8k16.row.col.f32.f16.f16.f32 " \
        "{%0,%1,%2,%3}, {%4,%5,%6,%7}, {%8,%9}, {%0,%1,%2,%3};" \
        : "+f"((d)[0]), "+f"((d)[1]), "+f"((d)[2]), "+f"((d)[3]) \
        : "r"((a)[0]), "r"((a)[1]), "r"((a)[2]), "r"((a)[3]), "r"(b0), "r"(b1))

// ===========================================================================
// Kernel 1: W = fp16( grid[Qidxs].reshape(m, n) )
// ===========================================================================
__global__ void dequant_kernel(const float* __restrict__ grid,
                               const int*   __restrict__ qidxs,
                               __half*      __restrict__ W) {
    int i = blockIdx.x * blockDim.x + threadIdx.x;
    if (i >= NCODE) return;
    int idx = qidxs[i];
    const float4* g4 = reinterpret_cast<const float4*>(grid) + (size_t)idx * 2;
    float4 a = g4[0], b = g4[1];
    __half2 h0 = __floats2half2_rn(a.x, a.y);
    __half2 h1 = __floats2half2_rn(a.z, a.w);
    __half2 h2 = __floats2half2_rn(b.x, b.y);
    __half2 h3 = __floats2half2_rn(b.z, b.w);
    uint4 o;
    o.x = *reinterpret_cast<uint32_t*>(&h0);
    o.y = *reinterpret_cast<uint32_t*>(&h1);
    o.z = *reinterpret_cast<uint32_t*>(&h2);
    o.w = *reinterpret_cast<uint32_t*>(&h3);
    reinterpret_cast<uint4*>(W)[i] = o;
}

// ===========================================================================
// FWHT, 3-pass radix-16: 256 threads, 16 elems/thread in registers.
// Padded smem phys(e) = e + (e>>4) -> conflict-free for all 3 passes.
// ===========================================================================
__device__ __forceinline__ void fwht16(float v[16]) {
    #pragma unroll
    for (int h = 1; h < 16; h <<= 1) {
        #pragma unroll
        for (int j = 0; j < 16; j += 2 * h) {
            #pragma unroll
            for (int k = 0; k < h; k++) {
                float a = v[j + k], b = v[j + k + h];
                v[j + k]     = a + b;
                v[j + k + h] = a - b;
            }
        }
    }
}

__global__ __launch_bounds__(256)
void fwht_su_kernel(const float* __restrict__ in,
                    const float* __restrict__ su,
                    __half*      __restrict__ out) {
    __shared__ float s[4096 + 256];
    const int t = threadIdx.x;
    const size_t row = blockIdx.x;
    float v[16];
    const float4* in4 = reinterpret_cast<const float4*>(in + row * NDIM) + t * 4;
    const float4* su4 = reinterpret_cast<const float4*>(su) + t * 4;
    #pragma unroll
    for (int i = 0; i < 4; i++) {
        float4 a = in4[i], b = su4[i];
        v[4*i+0] = a.x * b.x; v[4*i+1] = a.y * b.y;
        v[4*i+2] = a.z * b.z; v[4*i+3] = a.w * b.w;
    }
    fwht16(v);                                   // bits 0-3
    #pragma unroll
    for (int i = 0; i < 16; i++) s[17 * t + i] = v[i];
    __syncthreads();
    const int r = t & 15, q = t >> 4;
    const int b2 = 272 * q + r;
    #pragma unroll
    for (int i = 0; i < 16; i++) v[i] = s[b2 + 17 * i];
    fwht16(v);                                   // bits 4-7
    #pragma unroll
    for (int i = 0; i < 16; i++) s[b2 + 17 * i] = v[i];
    __syncthreads();
    const int b3 = t + (t >> 4);
    #pragma unroll
    for (int i = 0; i < 16; i++) v[i] = s[b3 + 272 * i];
    fwht16(v);                                   // bits 8-11
    __half* o = out + row * NDIM + t;
    #pragma unroll
    for (int i = 0; i < 16; i++) o[256 * i] = __float2half_rn(v[i] * 0.015625f);
}

__global__ __launch_bounds__(256)
void fwht_sv_kernel(float* __restrict__ data, const float* __restrict__ sv) {
    __shared__ float s[4096 + 256];
    const int t = threadIdx.x;
    const size_t row = blockIdx.x;
    float v[16];
    const float4* d4 = reinterpret_cast<const float4*>(data + row * MDIM) + t * 4;
    #pragma unroll
    for (int i = 0; i < 4; i++) {
        float4 a = d4[i];
        v[4*i+0] = a.x; v[4*i+1] = a.y; v[4*i+2] = a.z; v[4*i+3] = a.w;
    }
    fwht16(v);
    #pragma unroll
    for (int i = 0; i < 16; i++) s[17 * t + i] = v[i];
    __syncthreads();
    const int r = t & 15, q = t >> 4;
    const int b2 = 272 * q + r;
    #pragma unroll
    for (int i = 0; i < 16; i++) v[i] = s[b2 + 17 * i];
    fwht16(v);
    #pragma unroll
    for (int i = 0; i < 16; i++) s[b2 + 17 * i] = v[i];
    __syncthreads();
    const int b3 = t + (t >> 4);
    #pragma unroll
    for (int i = 0; i < 16; i++) v[i] = s[b3 + 272 * i];
    fwht16(v);
    float* o = data + row * MDIM + t;
    const float* svp = sv + t;
    #pragma unroll
    for (int i = 0; i < 16; i++) o[256 * i] = v[i] * svp[256 * i] * 0.015625f;
}

// ===========================================================================
// Kernel 3: fp16 mma.sync GEMM  C[4096,4096] = A @ B^T (both K-major fp16)
// CTA tile 128x128x64; 4 warps (2M x 2N), warp tile 64x64.
// 3-stage cp.async pipeline, cross-tile fragment pipelining,
// ONE __syncthreads per k-tile (CUTLASS sm80 schedule).
// ===========================================================================
#define NST      3
#define A_ST     (128 * 128)          // bytes per A stage
#define B_ST     (128 * 128)
#define STG      (A_ST + B_ST)        // 32 KB
#define GEMM_SMEM (NST * STG + 1024)  // 97 KB

__device__ __forceinline__ void load_stage(uint32_t s0, int st, int kt, int tid,
                                           const __half* Ab, const __half* Bb) {
    uint32_t sA = s0 + st * STG;
    uint32_t sB = sA + A_ST;
    #pragma unroll
    for (int it = 0; it < 16; it++) {
        int c = tid + it * 128;                  // 0..2047
        if (c < 1024) {                          // A: 128 rows x 8 chunks(16B)
            int rr = c >> 3, cc = c & 7;
            cp_async16(sA + SWZ(rr * 128 + cc * 16),
                       Ab + (size_t)rr * NDIM + kt * 64 + cc * 8);
        } else {                                 // B
            int b = c - 1024;
            int rr = b >> 3, cc = b & 7;
            cp_async16(sB + SWZ(rr * 128 + cc * 16),
                       Bb + (size_t)rr * NDIM + kt * 64 + cc * 8);
        }
    }
    CP_COMMIT();
}

__global__ __launch_bounds__(128, 2)
void gemm_fp16(const __half* __restrict__ A,
               const __half* __restrict__ B,
               float*        __restrict__ C) {
    extern __shared__ char smraw[];
    const uint32_t s0 = (smem_u32(smraw) + 1023u) & ~1023u;
    const int tid  = threadIdx.x;
    const int wid  = tid >> 5;
    const int lane = tid & 31;
    const int g    = lane >> 2;
    const int t4   = lane & 3;
    const int wm   = (wid & 1) * 64;
    const int wn   = (wid >> 1) * 64;

    // ldmatrix lane-address selectors (validated round 6)
    const int a_row = (lane & 7) + ((lane & 8)  ? 8 : 0);
    const int a_kx  = (lane & 16) ? 16 : 0;
    const int b_row = (lane & 7) + ((lane & 16) ? 8 : 0);
    const int b_kx  = (lane & 8)  ? 16 : 0;

    const __half* Ab = A + (size_t)(blockIdx.y * 128) * NDIM;
    const __half* Bb = B + (size_t)(blockIdx.x * 128) * NDIM;

    float c[4][8][4];
    #pragma unroll
    for (int i = 0; i < 4; i++)
        #pragma unroll
        for (int j = 0; j < 8; j++)
            #pragma unroll
            for (int k = 0; k < 4; k++) c[i][j][k] = 0.f;

    uint32_t af[2][4][4], bf[2][8][2];

    // fragment-load helper (buf = destination buffer, base = stage smem, kb = k-byte offset)
    #define LOAD_FRAGS(buf, base, kb) do {                                      \
        const uint32_t _sA = (base);                                            \
        const uint32_t _sB = _sA + A_ST;                                        \
        _Pragma("unroll")                                                       \
        for (int mi = 0; mi < 4; mi++) {                                        \
            int row = wm + mi * 16 + a_row;                                     \
            uint32_t ad = _sA + row * 128 + (((kb) + a_kx) ^ ((row & 7) << 4)); \
            LDSM4(af[buf][mi][0], af[buf][mi][1], af[buf][mi][2], af[buf][mi][3], ad); \
        }                                                                       \
        _Pragma("unroll")                                                       \
        for (int nb = 0; nb < 4; nb++) {                                        \
            int row = wn + nb * 16 + b_row;                                     \
            uint32_t bd = _sB + row * 128 + (((kb) + b_kx) ^ ((row & 7) << 4)); \
            LDSM4(bf[buf][2*nb][0], bf[buf][2*nb][1],                           \
                  bf[buf][2*nb+1][0], bf[buf][2*nb+1][1], bd);                  \
        }                                                                       \
    } while (0)

    // prologue: stages 0,1 in flight; wait stage 0; warm fragment buffer 0
    load_stage(s0, 0, 0, tid, Ab, Bb);
    load_stage(s0, 1, 1, tid, Ab, Bb);
    CP_WAIT1();
    __syncthreads();
    LOAD_FRAGS(0, s0, 0);

    const int KT = NDIM / 64;   // 64 k-tiles
    for (int kt = 0; kt < KT; kt++) {
        const uint32_t stage_cur = s0 + (kt % NST) * STG;
        const uint32_t stage_nxt = s0 + ((kt + 1) % NST) * STG;
        #pragma unroll
        for (int ks = 0; ks < 4; ks++) {
            const int cur = ks & 1, nxt = cur ^ 1;
            if (ks == 3) {
                // stage kt+1 must be resident before cross-tile prefetch;
                // sync also protects stage (kt+2)%NST from early overwrite
                if (kt + 1 < KT) {
                    CP_WAIT1();
                    __syncthreads();
                    LOAD_FRAGS(nxt, stage_nxt, 0);
                }
            } else {
                LOAD_FRAGS(nxt, stage_cur, (ks + 1) * 32);
            }
            if (ks == 0) {
                if (kt + 2 < KT) load_stage(s0, (kt + 2) % NST, kt + 2, tid, Ab, Bb);
                else             CP_COMMIT();    // empty group keeps wait_group 1 exact
            }
            #pragma unroll
            for (int mi = 0; mi < 4; mi++)
                #pragma unroll
                for (int ni = 0; ni < 8; ni++)
                    MMA16816(c[mi][ni], af[cur][mi], bf[cur][ni][0], bf[cur][ni][1]);
        }
    }
    #undef LOAD_FRAGS

    // epilogue
    float* Cb = C + (size_t)(blockIdx.y * 128 + wm) * MDIM + blockIdx.x * 128 + wn;
    #pragma unroll
    for (int mi = 0; mi < 4; mi++) {
        #pragma unroll
        for (int ni = 0; ni < 8; ni++) {
            const int col = ni * 8 + 2 * t4;
            *reinterpret_cast<float2*>(Cb + (size_t)(mi * 16 + g    ) * MDIM + col) =
                make_float2(c[mi][ni][0], c[mi][ni][1]);
            *reinterpret_cast<float2*>(Cb + (size_t)(mi * 16 + g + 8) * MDIM + col) =
                make_float2(c[mi][ni][2], c[mi][ni][3]);
        }
    }
}

// ===========================================================================
// Launch: input, SU, SV, grid, Qidxs (metadata order)
// ===========================================================================
extern "C" void kernel_launch(void* const* d_in, const int* in_sizes, int n_in,
                              void* d_out, int out_size) {
    const float* input = (const float*)d_in[0];
    const float* SU    = (const float*)d_in[1];
    const float* SV    = (const float*)d_in[2];
    const float* grid  = (const float*)d_in[3];
    const int*   qidxs = (const int*)  d_in[4];
    float* out = (float*)d_out;

    __half* Xh = nullptr;
    __half* W  = nullptr;
    cudaGetSymbolAddress((void**)&Xh, g_Xh);
    cudaGetSymbolAddress((void**)&W,  g_W);

    cudaFuncSetAttribute(gemm_fp16, cudaFuncAttributeMaxDynamicSharedMemorySize, GEMM_SMEM);

    // 1. dequantize codebook -> W (fp16)
    dequant_kernel<<<(NCODE + 255) / 256, 256>>>(grid, qidxs, W);

    // 2. Xh = fp16( FWHT(input * SU) / 64 )
    fwht_su_kernel<<<ROWS_T, 256>>>(input, SU, Xh);

    // 3. out = Xh @ W^T  (fp16 mma.sync, fp32 accumulate)
    dim3 gdim(MDIM / 128, ROWS_T / 128);
    gemm_fp16<<<gdim, 128, GEMM_SMEM>>>(Xh, W, out);

    // 4. out = FWHT(out) * SV / 64   (in place)
    fwht_sv_kernel<<<ROWS_T, 256>>>(out, SV);
}